// round 17
// baseline (speedup 1.0000x reference)
#include <cuda_runtime.h>
#include <cuda_bf16.h>

#define BN 512
#define VN 778
#define FN 1538
#define PN 1024
#define NRED 22
#define GRID (2 * BN)

typedef unsigned long long u64;

// Device scratch (no allocations allowed)
__device__ float g_part[NRED * BN];
__device__ unsigned int g_cnt = 0;

__device__ __forceinline__ float warpReduceSum(float v) {
#pragma unroll
    for (int o = 16; o > 0; o >>= 1) v += __shfl_down_sync(0xffffffffu, v, o);
    return v;
}

// phi = sum_k relu(-h_k) * exp(-2*rho2_k); exp(-2x) = exp2(K2*x)
__device__ __forceinline__ float coneFieldV(float4 t0, float4 t1, float4 t2,
                                            float4 q0, float4 q1, float4 q2) {
    const float third = 1.0f / 3.0f;
    const float K2 = -2.8853900817779268f;
    float cx = (t0.x + t1.x + t2.x) * third;
    float cy = (t0.y + t1.y + t2.y) * third;
    float cz = (t0.z + t1.z + t2.z) * third;
    float e1x = t1.x - t0.x, e1y = t1.y - t0.y, e1z = t1.z - t0.z;
    float e2x = t2.x - t0.x, e2y = t2.y - t0.y, e2z = t2.z - t0.z;
    float nx = e1y * e2z - e1z * e2y;
    float ny = e1z * e2x - e1x * e2z;
    float nz = e1x * e2y - e1y * e2x;
    float inv = rsqrtf(nx * nx + ny * ny + nz * nz + 1e-18f);
    nx *= inv; ny *= inv; nz *= inv;

    float s = 0.0f;
    {
        float dx = q0.x - cx, dy = q0.y - cy, dz = q0.z - cz;
        float h = dx * nx + dy * ny + dz * nz;
        float rho2 = fmaxf(dx * dx + dy * dy + dz * dz - h * h, 0.0f);
        s += fmaxf(-h, 0.0f) * exp2f(rho2 * K2);
    }
    {
        float dx = q1.x - cx, dy = q1.y - cy, dz = q1.z - cz;
        float h = dx * nx + dy * ny + dz * nz;
        float rho2 = fmaxf(dx * dx + dy * dy + dz * dz - h * h, 0.0f);
        s += fmaxf(-h, 0.0f) * exp2f(rho2 * K2);
    }
    {
        float dx = q2.x - cx, dy = q2.y - cy, dz = q2.z - cz;
        float h = dx * nx + dy * ny + dz * nz;
        float rho2 = fmaxf(dx * dx + dy * dy + dz * dz - h * h, 0.0f);
        s += fmaxf(-h, 0.0f) * exp2f(rho2 * K2);
    }
    return s;
}

// Dynamic smem: verts as float4 (2*VN) + faces as u64 (3 x 16-bit ids, offset folded)
#define SMEM_BYTES (2 * VN * 16 + 2 * FN * 8)

__global__ void __launch_bounds__(256)
fused_kernel(const float* __restrict__ verts,  const int* __restrict__ faces,
             const int* __restrict__ cidx,
             const float* __restrict__ betas,  const float* __restrict__ transl,
             const float* __restrict__ j3d,    const float* __restrict__ go,
             const float* __restrict__ pose,   const float* __restrict__ ttrans,
             const float* __restrict__ tj3d,   const float* __restrict__ tgo,
             const float* __restrict__ tpose,  const float* __restrict__ tshape,
             const float* __restrict__ logits, const int* __restrict__ handed,
             const int* __restrict__ valid,    const int* __restrict__ ctgt,
             float* __restrict__ out) {
    extern __shared__ char dyn[];
    float4* sv = (float4*)dyn;               // 2*VN float4
    u64* sfp = (u64*)(sv + 2 * VN);          // 2*FN packed faces (u64)

    __shared__ float swarp[8];
    __shared__ float sred[NRED][8];

    int j = threadIdx.x;
    int wid = j >> 5;
    int lane = j & 31;

    if (blockIdx.x < BN) {
        // ================= collision block =================
        int b = blockIdx.x;

        // prefetch pair indices: thread j owns pairs 4j..4j+3 (2 x LDG.128)
        const int4* c4 = (const int4*)(cidx + (size_t)b * PN * 2);
        int4 pA = __ldg(c4 + 2 * j);
        int4 pB = __ldg(c4 + 2 * j + 1);
        int2 pi[4] = { make_int2(pA.x, pA.y), make_int2(pA.z, pA.w),
                       make_int2(pB.x, pB.y), make_int2(pB.z, pB.w) };

        // stage verts via float2 (rows are 12B, 8B-aligned): 2 verts / 3 ld.64
        // VN = 778 = 2 * 389 groups per hand
        {
            const float2* w0 = (const float2*)(verts + (size_t)b * VN * 3);
            const float2* w1 = (const float2*)(verts + (size_t)(BN + b) * VN * 3);
            for (int g = j; g < 389; g += 256) {
                float2 x0 = __ldg(w0 + 3 * g);
                float2 x1 = __ldg(w0 + 3 * g + 1);
                float2 x2 = __ldg(w0 + 3 * g + 2);
                sv[2 * g]     = make_float4(x0.x, x0.y, x1.x, 0.0f);
                sv[2 * g + 1] = make_float4(x1.y, x2.x, x2.y, 0.0f);
                float2 y0 = __ldg(w1 + 3 * g);
                float2 y1 = __ldg(w1 + 3 * g + 1);
                float2 y2 = __ldg(w1 + 3 * g + 2);
                sv[VN + 2 * g]     = make_float4(y0.x, y0.y, y1.x, 0.0f);
                sv[VN + 2 * g + 1] = make_float4(y1.y, y2.x, y2.y, 0.0f);
            }
        }
        // stage faces as u64: 3 x 16-bit ids with +VN hand offset folded in.
        // 3 int4 -> 4 faces, 2*FN = 4*769
        {
            const int4* f4 = (const int4*)faces;
            for (int g = j; g < 769; g += 256) {
                int4 a = __ldg(f4 + 3 * g);
                int4 c0 = __ldg(f4 + 3 * g + 1);
                int4 c1 = __ldg(f4 + 3 * g + 2);
                int fi = 4 * g;
                unsigned o0 = (fi + 0 >= FN) ? VN : 0;
                unsigned o1 = (fi + 1 >= FN) ? VN : 0;
                unsigned o2 = (fi + 2 >= FN) ? VN : 0;
                unsigned o3 = (fi + 3 >= FN) ? VN : 0;
                sfp[fi + 0] = (u64)((unsigned)a.x + o0) |
                              ((u64)((unsigned)a.y + o0) << 16) |
                              ((u64)((unsigned)a.z + o0) << 32);
                sfp[fi + 1] = (u64)((unsigned)a.w + o1) |
                              ((u64)((unsigned)c0.x + o1) << 16) |
                              ((u64)((unsigned)c0.y + o1) << 32);
                sfp[fi + 2] = (u64)((unsigned)c0.z + o2) |
                              ((u64)((unsigned)c0.w + o2) << 16) |
                              ((u64)((unsigned)c1.x + o2) << 32);
                sfp[fi + 3] = (u64)((unsigned)c1.y + o3) |
                              ((u64)((unsigned)c1.z + o3) << 16) |
                              ((u64)((unsigned)c1.w + o3) << 32);
            }
        }
        __syncthreads();

        // pairs: branch-skip (invalid lanes issue no LDS)
        float acc = 0.0f;
#pragma unroll
        for (int it = 0; it < 4; it++) {
            int2 ii = pi[it];
            if ((ii.x | ii.y) >= 0) {
                u64 wa = sfp[ii.x];
                u64 wb = sfp[ii.y];
                float4 A0 = sv[(unsigned)(wa & 0xFFFFu)];
                float4 A1 = sv[(unsigned)((wa >> 16) & 0xFFFFu)];
                float4 A2 = sv[(unsigned)(wa >> 32)];
                float4 B0 = sv[(unsigned)(wb & 0xFFFFu)];
                float4 B1 = sv[(unsigned)((wb >> 16) & 0xFFFFu)];
                float4 B2 = sv[(unsigned)(wb >> 32)];
                acc += coneFieldV(A0, A1, A2, B0, B1, B2) +
                       coneFieldV(B0, B1, B2, A0, A1, A2);
            }
        }

        float w = warpReduceSum(acc);
        if (lane == 0) swarp[wid] = w;
        __syncthreads();
        if (j == 0) {
            float t = 0.0f;
#pragma unroll
            for (int i = 0; i < 8; i++) t += swarp[i];
            g_part[0 * BN + b] = t;
            g_part[1 * BN + b] = (t != 0.0f) ? 1.0f : 0.0f;
        }
    } else {
        // ================= small-loss block =================
        int b = blockIdx.x - BN;

        float a[NRED];
#pragma unroll
        for (int i = 0; i < NRED; i++) a[i] = 0.0f;

        if (j < 64) {
            float fint = ((__ldg(handed + b * 2) + __ldg(handed + b * 2 + 1)) == 2)
                             ? 1.0f : 0.0f;
            if (j == 0) a[2] = fint;

            if (j < 10) {
                float d = betas[b * 10 + j] - betas[(BN + b) * 10 + j];
                a[3] = fint * d * d;
            }
            if (j < 3) {
                float d = (transl[b * 3 + j] - transl[(BN + b) * 3 + j]) -
                          (ttrans[b * 3 + j] - ttrans[(BN + b) * 3 + j]);
                a[4] = fint * d * d;
            }
            if (j < 63) {
                float d = (j3d[b * 63 + j] - j3d[(BN + b) * 63 + j]) -
                          (tj3d[b * 63 + j] - tj3d[(BN + b) * 63 + j]);
                a[5] = fint * d * d;
            }

#pragma unroll
            for (int h = 0; h < 2; h++) {
                int bs = 6 + 7 * h;
                float m = (float)__ldg(valid + h * BN + b);
                if (j == 0) a[bs + 0] = m;

                if (j < 3) {
                    float d = go[(h * BN + b) * 3 + j] - tgo[(h * BN + b) * 3 + j];
                    a[bs + 1] = m * d * d;
                }
                if (j < 45) {
                    float d = pose[(h * BN + b) * 45 + j] - tpose[(h * BN + b) * 45 + j];
                    a[bs + 2] = m * d * d;
                }
                if (j < 63) {
                    const float* jo = j3d  + (size_t)(h * BN + b) * 63;
                    const float* jt = tj3d + (size_t)(h * BN + b) * 63;
                    float o = jo[j], t = jt[j];
                    if (j >= 3) {
                        int c = j % 3;
                        float d = (o - jo[c]) * 1000.0f - (t - jt[c]) * 1000.0f;
                        a[bs + 3] = m * fabsf(d);
                    }
                    a[bs + 4] = m * fabsf(o * 1000.0f - t * 1000.0f);
                }
                if (j < 10) {
                    float d = betas[(h * BN + b) * 10 + j] - tshape[(h * BN + b) * 10 + j];
                    a[bs + 5] = m * d * d;
                }
                if (j < 3) {
                    float d = transl[(h * BN + b) * 3 + j] - ttrans[(h * BN + b) * 3 + j];
                    a[bs + 6] = m * fabsf(d);
                }
            }

            if (j == 0) {
                const float* lg = logits + b * 4;
                float l0 = lg[0], l1 = lg[1], l2 = lg[2], l3 = lg[3];
                float mx = fmaxf(fmaxf(l0, l1), fmaxf(l2, l3));
                float se = __expf(l0 - mx) + __expf(l1 - mx) +
                           __expf(l2 - mx) + __expf(l3 - mx);
                float lse = logf(se);
                int t = __ldg(ctgt + b);
                float lt = (t == 0) ? l0 : (t == 1) ? l1 : (t == 2) ? l2 : l3;
                float nll = -(lt - mx - lse);
                const float wts[4] = {1.0f, 30.0f, 30.0f, 10.0f};
                float wv = wts[t] * ((t != 0) ? 1.0f : 0.0f);
                a[20] = wv * nll;
                a[21] = wv;
            }

            // reduce slots 2..21 across warps 0-1
#pragma unroll
            for (int i = 2; i < NRED; i++) {
                float v = warpReduceSum(a[i]);
                if (lane == 0) sred[i][wid] = v;
            }
        }
        __syncthreads();
        if (j >= 2 && j < NRED)
            g_part[j * BN + b] = sred[j][0] + sred[j][1];
    }

    // ---- last of all GRID blocks folds the final reduction ----
    __threadfence();
    __syncthreads();
    __shared__ bool isLast;
    if (j == 0)
        isLast = (atomicAdd(&g_cnt, 1u) == (unsigned)(GRID - 1));
    __syncthreads();
    if (!isLast) return;
    __threadfence();  // acquire all blocks' g_part writes

    float r[NRED];
#pragma unroll
    for (int i = 0; i < NRED; i++)
        r[i] = g_part[i * BN + j] + g_part[i * BN + 256 + j];

    __syncthreads();  // reuse sred safely
#pragma unroll
    for (int i = 0; i < NRED; i++) {
        float v = warpReduceSum(r[i]);
        if (lane == 0) sred[i][wid] = v;
    }
    __syncthreads();

    if (j == 0) {
        g_cnt = 0;  // reset for next graph replay
        float s[NRED];
#pragma unroll
        for (int i = 0; i < NRED; i++) {
            float t = 0.0f;
#pragma unroll
            for (int k = 0; k < 8; k++) t += sred[i][k];
            s[i] = t;
        }
        auto il = [](float sum, float denom) -> float {
            return (denom > 0.0f) ? sum / fmaxf(denom, 1.0f) : 0.0f;
        };

        out[0] = (s[1] > 0.0f) ? (s[0] / fmaxf(s[1], 1.0f)) * 100.0f : 0.0f;
        float ic = s[2];
        out[1] = il(s[3], ic * 10.0f);
        out[2] = il(s[4], ic * 3.0f) * 100.0f;
        out[3] = il(s[5], ic * 63.0f) * 100.0f;

        float lgo = 0, lhp = 0, lrj = 0, lj3 = 0, lsh = 0, ltr = 0;
#pragma unroll
        for (int h = 0; h < 2; h++) {
            int bs = 6 + 7 * h;
            float c = s[bs + 0];
            lgo += il(s[bs + 1], c * 3.0f)  * 10.0f;
            lhp += il(s[bs + 2], c * 45.0f) * 10.0f;
            lrj += il(s[bs + 3], c * 60.0f) * 0.01f;
            lj3 += il(s[bs + 4], c * 63.0f) * 0.01f;
            lsh += il(s[bs + 5], c * 10.0f) * 10.0f;
            ltr += il(s[bs + 6], c * 3.0f)  * 10.0f;
        }
        out[4] = lgo;
        out[5] = lhp;
        out[6] = lrj;
        out[7] = lj3;
        out[8] = lsh;
        out[9] = ltr;
        out[10] = 0.0f;  // mse(x,x) == 0 exactly
        out[11] = s[20] / fmaxf(s[21], 1e-9f);
    }
}

extern "C" void kernel_launch(void* const* d_in, const int* in_sizes, int n_in,
                              void* d_out, int out_size) {
    const float* verts  = (const float*)d_in[0];
    const float* betas  = (const float*)d_in[1];
    const float* transl = (const float*)d_in[2];
    const float* j3d    = (const float*)d_in[3];
    const float* go     = (const float*)d_in[4];
    const float* pose   = (const float*)d_in[5];
    const float* ttrans = (const float*)d_in[6];
    const float* tj3d   = (const float*)d_in[7];
    const float* tgo    = (const float*)d_in[8];
    const float* tpose  = (const float*)d_in[9];
    const float* tshape = (const float*)d_in[10];
    const float* logits = (const float*)d_in[11];
    const int*   faces  = (const int*)d_in[12];
    const int*   cidx   = (const int*)d_in[13];
    const int*   handed = (const int*)d_in[14];
    const int*   valid  = (const int*)d_in[15];
    const int*   ctgt   = (const int*)d_in[16];

    static bool attr_set = false;
    if (!attr_set) {
        cudaFuncSetAttribute(fused_kernel,
                             cudaFuncAttributeMaxDynamicSharedMemorySize,
                             SMEM_BYTES);
        attr_set = true;
    }

    fused_kernel<<<GRID, 256, SMEM_BYTES>>>(verts, faces, cidx, betas, transl,
                                            j3d, go, pose, ttrans, tj3d, tgo,
                                            tpose, tshape, logits, handed, valid,
                                            ctgt, (float*)d_out);
}